// round 17
// baseline (speedup 1.0000x reference)
#include <cuda_runtime.h>
#include <cuda_fp16.h>
#include <mma.h>
#include <math.h>

using namespace nvcuda;

#define N_NODES   100000
#define N_EDGES   1600000
#define E_TOT     (N_EDGES + N_NODES)
#define IN_CH     128
#define HID       64
#define OUT_CH    16
#define N_GRAPHS  512
#define NEG_SLOPE 0.2f

#define SCAN_BLK  512
#define N_SCAN_BLKS ((N_NODES + SCAN_BLK - 1) / SCAN_BLK)   // 196
#define N_TILES   (N_NODES / 16)                            // 6250
#define MMA_GRID  196

// ---------------- scratch (device globals; no allocation allowed) ----------------
__device__ __half2 g_xl[(size_t)N_NODES * 32];
__device__ __half2 g_xr[(size_t)N_NODES * 32];
__device__ __half  g_xh[(size_t)N_NODES * IN_CH];   // fp16 x
__device__ __half  g_hh[(size_t)N_NODES * HID];     // fp16 hidden
__device__ __half  g_w1h[2 * IN_CH * HID];          // fp16 Wl1|Wr1
__device__ __half  g_w2h[2 * HID * HID];            // fp16 Wl2|Wr2
__device__ float   g_pool[N_GRAPHS * HID];
__device__ float   g_cnt[N_GRAPHS];
__device__ float   g_y[N_GRAPHS * HID];
__device__ float   g_bnstat[2 * HID];
__device__ int     g_is64;

// CSR scratch
__device__ int g_deg[N_NODES];
__device__ int g_rowptr[N_NODES + 1];
__device__ int g_cursor[N_NODES];
__device__ int g_col[E_TOT];
__device__ int g_bsum[N_SCAN_BLKS];

// ---------------- aux streams/events ----------------
namespace {
struct Aux {
    cudaStream_t s2 = nullptr;
    cudaEvent_t  evFork = nullptr, evB = nullptr;
    Aux() {
        if (cudaStreamCreateWithFlags(&s2, cudaStreamNonBlocking) != cudaSuccess) {
            s2 = nullptr; return;
        }
        if (cudaEventCreateWithFlags(&evFork, cudaEventDisableTiming) != cudaSuccess) {
            evFork = nullptr; return;
        }
        if (cudaEventCreateWithFlags(&evB, cudaEventDisableTiming) != cudaSuccess) {
            evB = nullptr; return;
        }
    }
};
Aux g_aux;
}

__device__ __forceinline__ unsigned h2u(__half2 h) { return *(unsigned*)&h; }
__device__ __forceinline__ __half2 u2h(unsigned u) { return *(__half2*)&u; }

// ---------------- dtype detection ----------------
__global__ void detect_kernel(const int* __restrict__ w) {
    int ok64 = 1;
    for (int i = 0; i < 32; i++)
        if (w[2 * i + 1] != 0) ok64 = 0;
    g_is64 = ok64;
}

__device__ __forceinline__ int load_idx(const void* p, long long i) {
    if (g_is64) return (int)((const long long*)p)[i];
    return ((const int*)p)[i];
}

// ---------------- conversions ----------------
__global__ void convert_w_kernel(const float* __restrict__ wl1, const float* __restrict__ wr1,
                                 const float* __restrict__ wl2, const float* __restrict__ wr2,
                                 __half* __restrict__ w1h, __half* __restrict__ w2h) {
    int i = blockIdx.x * blockDim.x + threadIdx.x;
    if (i < IN_CH * HID) {
        w1h[i]                = __float2half(wl1[i]);
        w1h[IN_CH * HID + i]  = __float2half(wr1[i]);
    }
    if (i < HID * HID) {
        w2h[i]               = __float2half(wl2[i]);
        w2h[HID * HID + i]   = __float2half(wr2[i]);
    }
}

__global__ void convert_x_kernel(const float* __restrict__ X, __half2* __restrict__ XH) {
    size_t i = (size_t)blockIdx.x * blockDim.x + threadIdx.x;   // 4 floats each
    if (i * 4 >= (size_t)N_NODES * IN_CH) return;
    float4 v = ((const float4*)X)[i];
    XH[2 * i]     = __floats2half2_rn(v.x, v.y);
    XH[2 * i + 1] = __floats2half2_rn(v.z, v.w);
}

// ---------------- CSR build ----------------
__global__ void hist_kernel(const void* __restrict__ ei, int* __restrict__ deg) {
    int t = blockIdx.x * blockDim.x + threadIdx.x;
#pragma unroll
    for (int u = 0; u < 2; u++) {
        int e = t * 2 + u;
        if (e >= E_TOT) return;
        int dst = (e < N_EDGES) ? load_idx(ei, (long long)N_EDGES + e) : e - N_EDGES;
        atomicAdd(&deg[dst], 1);
    }
}

__global__ void scan1_kernel(const int* __restrict__ deg, int* __restrict__ rowptr,
                             int* __restrict__ bsum) {
    __shared__ int sh[SCAN_BLK];
    int i = blockIdx.x * SCAN_BLK + threadIdx.x;
    int v = (i < N_NODES) ? deg[i] : 0;
    sh[threadIdx.x] = v;
    __syncthreads();
    for (int o = 1; o < SCAN_BLK; o <<= 1) {
        int t = (threadIdx.x >= o) ? sh[threadIdx.x - o] : 0;
        __syncthreads();
        sh[threadIdx.x] += t;
        __syncthreads();
    }
    if (i < N_NODES) rowptr[i] = sh[threadIdx.x] - v;
    if (threadIdx.x == SCAN_BLK - 1) bsum[blockIdx.x] = sh[SCAN_BLK - 1];
}

__global__ void scan2_kernel(int* __restrict__ bsum) {
    int lane = threadIdx.x & 31;
    int acc = 0;
    for (int base = 0; base < N_SCAN_BLKS; base += 32) {
        int i = base + lane;
        int orig = (i < N_SCAN_BLKS) ? bsum[i] : 0;
        int v = orig;
#pragma unroll
        for (int o = 1; o < 32; o <<= 1) {
            int t = __shfl_up_sync(0xffffffffu, v, o);
            if (lane >= o) v += t;
        }
        if (i < N_SCAN_BLKS) bsum[i] = acc + v - orig;
        acc += __shfl_sync(0xffffffffu, v, 31);
    }
}

__global__ void scan3_kernel(int* __restrict__ rowptr, const int* __restrict__ bsum,
                             int* __restrict__ cursor) {
    int i = blockIdx.x * SCAN_BLK + threadIdx.x;
    if (i < N_NODES) {
        int v = rowptr[i] + bsum[blockIdx.x];
        rowptr[i] = v;
        cursor[i] = v;
    }
    if (i == 0) rowptr[N_NODES] = E_TOT;
}

__global__ void scatter_kernel(const void* __restrict__ ei,
                               int* __restrict__ cursor, int* __restrict__ col) {
    int t = blockIdx.x * blockDim.x + threadIdx.x;
#pragma unroll
    for (int u = 0; u < 2; u++) {
        int e = t * 2 + u;
        if (e >= E_TOT) return;
        int src, dst;
        if (e < N_EDGES) {
            src = load_idx(ei, e);
            dst = load_idx(ei, (long long)N_EDGES + e);
        } else {
            src = dst = e - N_EDGES;
        }
        int pos = atomicAdd(&cursor[dst], 1);
        col[pos] = src;
    }
}

// ---------------- dual linear via wmma, weight-amortized tile loop -----------
// Block: 8 warps.  W staged fp16 in smem ONCE; each warp loops over node
// tiles (16 nodes x 64 ch for both Wl and Wr).
template <int IN>
__global__ __launch_bounds__(256) void dual_linear_mma(
        const __half* __restrict__ A,       // [N, IN] fp16
        const __half* __restrict__ WH,      // [2*IN*64] fp16 (Wl | Wr)
        const float* __restrict__ bl, const float* __restrict__ br,
        __half2* __restrict__ XL, __half2* __restrict__ XR) {
    __shared__ __half ws[2 * IN * HID];
    __shared__ float  obuf[8][16 * 16];

    int warp = threadIdx.x >> 5;
    int lane = threadIdx.x & 31;

    for (int i = threadIdx.x; i < 2 * IN * HID; i += 256)
        ws[i] = WH[i];
    __syncthreads();

    for (int tile = blockIdx.x * 8 + warp; tile < N_TILES; tile += MMA_GRID * 8) {
        int nodeBase = tile * 16;

        wmma::fragment<wmma::accumulator, 16, 16, 16, float> accl[4], accr[4];
#pragma unroll
        for (int t = 0; t < 4; t++) {
            wmma::fill_fragment(accl[t], 0.0f);
            wmma::fill_fragment(accr[t], 0.0f);
        }

        for (int k = 0; k < IN; k += 16) {
            wmma::fragment<wmma::matrix_a, 16, 16, 16, __half, wmma::row_major> af;
            wmma::load_matrix_sync(af, A + (size_t)nodeBase * IN + k, IN);
#pragma unroll
            for (int t = 0; t < 4; t++) {
                wmma::fragment<wmma::matrix_b, 16, 16, 16, __half, wmma::row_major> bf;
                wmma::load_matrix_sync(bf, ws + k * HID + t * 16, HID);
                wmma::mma_sync(accl[t], af, bf, accl[t]);
                wmma::load_matrix_sync(bf, ws + IN * HID + k * HID + t * 16, HID);
                wmma::mma_sync(accr[t], af, bf, accr[t]);
            }
        }

        float* ob = obuf[warp];
#pragma unroll
        for (int m = 0; m < 2; m++) {
            __half2* OUT = m ? XR : XL;
            const float* bb = m ? br : bl;
#pragma unroll
            for (int t = 0; t < 4; t++) {
                wmma::store_matrix_sync(ob, m ? accr[t] : accl[t], 16, wmma::mem_row_major);
                __syncwarp();
                for (int idx = lane; idx < 128; idx += 32) {
                    int row = idx >> 3, cc = idx & 7;
                    float v0 = ob[row * 16 + cc * 2]     + bb[t * 16 + cc * 2];
                    float v1 = ob[row * 16 + cc * 2 + 1] + bb[t * 16 + cc * 2 + 1];
                    OUT[(size_t)(nodeBase + row) * 32 + t * 8 + cc] =
                        __floats2half2_rn(v0, v1);
                }
                __syncwarp();
            }
        }
    }
}

// ---------------- GAT aggregate: 4 nodes/warp, 8 lanes/node, half2 e-path,
// fp32 accumulators.  POOL_MODE=0 writes fp16 h; POOL_MODE=1 pools. ----------
template <int POOL_MODE>
__global__ __launch_bounds__(256) void gat_agg_kernel(
        const int* __restrict__ rowptr, const int* __restrict__ col,
        const __half2* __restrict__ XL, const __half2* __restrict__ XR,
        const float* __restrict__ att, const float* __restrict__ bias,
        __half2* __restrict__ OUTH, int do_relu,
        const void* __restrict__ batch, float* __restrict__ POOL,
        float* __restrict__ CNT) {
    int warp = threadIdx.x >> 5;
    int lane = threadIdx.x & 31;
    int q    = lane >> 3;
    int hl   = lane & 7;
    int node = blockIdx.x * 32 + warp * 4 + q;

    uint4 rraw = ((const uint4*)(XR + (size_t)node * 32))[hl];
    __half2 r0 = u2h(rraw.x), r1 = u2h(rraw.y), r2 = u2h(rraw.z), r3 = u2h(rraw.w);

    float4 aLo = ((const float4*)att)[2 * hl];
    float4 aHi = ((const float4*)att)[2 * hl + 1];
    __half2 at0 = __floats2half2_rn(aLo.x, aLo.y);
    __half2 at1 = __floats2half2_rn(aLo.z, aLo.w);
    __half2 at2 = __floats2half2_rn(aHi.x, aHi.y);
    __half2 at3 = __floats2half2_rn(aHi.z, aHi.w);
    const __half2 slope2 = __float2half2_rn(NEG_SLOPE);

    int beg = rowptr[node], end = rowptr[node + 1];
    int deg = end - beg;
    int m = deg;
    m = max(m, __shfl_xor_sync(0xffffffffu, m, 8));
    m = max(m, __shfl_xor_sync(0xffffffffu, m, 16));
    int maxit = m;

    float acc0 = 0.0f, acc1 = 0.0f, acc2 = 0.0f, acc3 = 0.0f;
    float acc4 = 0.0f, acc5 = 0.0f, acc6 = 0.0f, acc7 = 0.0f, z = 0.0f;

    int e = beg;
    for (int it = 0; it < maxit; it += 2, e += 2) {
        bool v[2] = { e < end, e + 1 < end };
        int s[2];
        s[0] = v[0] ? __ldg(&col[e])     : node;
        s[1] = v[1] ? __ldg(&col[e + 1]) : node;

        uint4 lraw[2];
        lraw[0] = ((const uint4*)(XL + (size_t)s[0] * 32))[hl];
        lraw[1] = ((const uint4*)(XL + (size_t)s[1] * 32))[hl];

        __half2 p2[2];
#pragma unroll
        for (int u = 0; u < 2; u++) {
            __half2 h0 = __hadd2(u2h(lraw[u].x), r0);
            __half2 h1 = __hadd2(u2h(lraw[u].y), r1);
            __half2 h2 = __hadd2(u2h(lraw[u].z), r2);
            __half2 h3 = __hadd2(u2h(lraw[u].w), r3);
            h0 = __hmax2(h0, __hmul2(h0, slope2));
            h1 = __hmax2(h1, __hmul2(h1, slope2));
            h2 = __hmax2(h2, __hmul2(h2, slope2));
            h3 = __hmax2(h3, __hmul2(h3, slope2));
            __half2 t = __hfma2(h0, at0, __hmul2(h1, at1));
            t = __hfma2(h2, at2, t);
            p2[u] = __hfma2(h3, at3, t);
        }
#pragma unroll
        for (int o = 4; o; o >>= 1) {
#pragma unroll
            for (int u = 0; u < 2; u++)
                p2[u] = __hadd2(p2[u], u2h(__shfl_xor_sync(0xffffffffu, h2u(p2[u]), o)));
        }
#pragma unroll
        for (int u = 0; u < 2; u++) {
            float2 pf = __half22float2(p2[u]);
            float w = v[u] ? __expf(pf.x + pf.y) : 0.0f;
            z += w;
            float2 f0 = __half22float2(u2h(lraw[u].x));
            float2 f1 = __half22float2(u2h(lraw[u].y));
            float2 f2 = __half22float2(u2h(lraw[u].z));
            float2 f3 = __half22float2(u2h(lraw[u].w));
            acc0 = fmaf(w, f0.x, acc0); acc1 = fmaf(w, f0.y, acc1);
            acc2 = fmaf(w, f1.x, acc2); acc3 = fmaf(w, f1.y, acc3);
            acc4 = fmaf(w, f2.x, acc4); acc5 = fmaf(w, f2.y, acc5);
            acc6 = fmaf(w, f3.x, acc6); acc7 = fmaf(w, f3.y, acc7);
        }
    }

    float inv = 1.0f / z;   // self-loop guarantees z > 0
    float4 bv0 = ((const float4*)bias)[2 * hl];
    float4 bv1 = ((const float4*)bias)[2 * hl + 1];
    float o0 = acc0 * inv + bv0.x;
    float o1 = acc1 * inv + bv0.y;
    float o2 = acc2 * inv + bv0.z;
    float o3 = acc3 * inv + bv0.w;
    float o4 = acc4 * inv + bv1.x;
    float o5 = acc5 * inv + bv1.y;
    float o6 = acc6 * inv + bv1.z;
    float o7 = acc7 * inv + bv1.w;

    if (POOL_MODE == 0) {
        if (do_relu) {
            o0 = fmaxf(o0, 0.0f); o1 = fmaxf(o1, 0.0f);
            o2 = fmaxf(o2, 0.0f); o3 = fmaxf(o3, 0.0f);
            o4 = fmaxf(o4, 0.0f); o5 = fmaxf(o5, 0.0f);
            o6 = fmaxf(o6, 0.0f); o7 = fmaxf(o7, 0.0f);
        }
        uint4 packed;
        packed.x = h2u(__floats2half2_rn(o0, o1));
        packed.y = h2u(__floats2half2_rn(o2, o3));
        packed.z = h2u(__floats2half2_rn(o4, o5));
        packed.w = h2u(__floats2half2_rn(o6, o7));
        ((uint4*)(OUTH + (size_t)node * 32))[hl] = packed;
    } else {
        int g = load_idx(batch, node);
        float* pp = &POOL[g * HID + hl * 8];
        asm volatile("red.global.add.v4.f32 [%0], {%1, %2, %3, %4};"
                     :: "l"(pp), "f"(o0), "f"(o1), "f"(o2), "f"(o3) : "memory");
        asm volatile("red.global.add.v4.f32 [%0], {%1, %2, %3, %4};"
                     :: "l"(pp + 4), "f"(o4), "f"(o5), "f"(o6), "f"(o7) : "memory");
        if (hl == 0) atomicAdd(&CNT[g], 1.0f);
    }
}

// ---------------- head: fc1 + batchnorm partial stats ----------------
__global__ void fc1_kernel(const float* __restrict__ POOL, const float* __restrict__ CNT,
                           const float* __restrict__ W, const float* __restrict__ b,
                           float* __restrict__ Y, float* __restrict__ BNSTAT) {
    int gi = blockIdx.x;
    int c  = threadIdx.x;
    __shared__ float gs[HID];
    float cnt = fmaxf(CNT[gi], 1.0f);
    gs[c] = POOL[gi * HID + c] / cnt;
    __syncthreads();
    float acc = b[c];
#pragma unroll 8
    for (int k = 0; k < HID; k++) acc = fmaf(gs[k], W[k * HID + c], acc);
    Y[gi * HID + c] = acc;
    atomicAdd(&BNSTAT[c], acc);
    atomicAdd(&BNSTAT[HID + c], acc * acc);
}

// ---------------- head: bn (inline stats) -> relu -> fc2 -> log_softmax -----
__global__ void head_kernel(const float* __restrict__ Y,
                            const float* __restrict__ BNSTAT,
                            const float* __restrict__ gamma, const float* __restrict__ beta,
                            const float* __restrict__ W2, const float* __restrict__ b2,
                            float* __restrict__ OUT) {
    int gi = blockIdx.x;
    int t  = threadIdx.x;
    __shared__ float ys[HID];
    __shared__ float os[OUT_CH];
    float s  = BNSTAT[t];
    float s2 = BNSTAT[HID + t];
    float mu  = s * (1.0f / N_GRAPHS);
    float var = s2 * (1.0f / N_GRAPHS) - mu * mu;
    float rsig = rsqrtf(var + 1e-5f);
    float v = Y[gi * HID + t];
    v = gamma[t] * (v - mu) * rsig + beta[t];
    ys[t] = fmaxf(v, 0.0f);
    __syncthreads();
    if (t < OUT_CH) {
        float acc = b2[t];
#pragma unroll 8
        for (int k = 0; k < HID; k++) acc = fmaf(ys[k], W2[k * OUT_CH + t], acc);
        os[t] = acc;
    }
    __syncthreads();
    if (t == 0) {
        float m = -1e30f;
#pragma unroll
        for (int j = 0; j < OUT_CH; j++) m = fmaxf(m, os[j]);
        float ssum = 0.0f;
#pragma unroll
        for (int j = 0; j < OUT_CH; j++) ssum += expf(os[j] - m);
        float lse = m + logf(ssum);
        for (int j = 0; j < OUT_CH; j++) OUT[gi * OUT_CH + j] = os[j] - lse;
    }
}

// ---------------- launch ----------------
extern "C" void kernel_launch(void* const* d_in, const int* in_sizes, int n_in,
                              void* d_out, int out_size) {
    const float* x      = (const float*)d_in[0];
    const void*  ei     = d_in[1];
    const void*  batch  = d_in[2];
    const float* W_l1   = (const float*)d_in[3];
    const float* b_l1   = (const float*)d_in[4];
    const float* W_r1   = (const float*)d_in[5];
    const float* b_r1   = (const float*)d_in[6];
    const float* att1   = (const float*)d_in[7];
    const float* bias1  = (const float*)d_in[8];
    const float* W_l2   = (const float*)d_in[9];
    const float* b_l2   = (const float*)d_in[10];
    const float* W_r2   = (const float*)d_in[11];
    const float* b_r2   = (const float*)d_in[12];
    const float* att2   = (const float*)d_in[13];
    const float* bias2  = (const float*)d_in[14];
    const float* W_fc1  = (const float*)d_in[15];
    const float* b_fc1  = (const float*)d_in[16];
    const float* gamma  = (const float*)d_in[17];
    const float* beta   = (const float*)d_in[18];
    const float* W_fc2  = (const float*)d_in[19];
    const float* b_fc2  = (const float*)d_in[20];
    float*       out    = (float*)d_out;

    __half2 *xl, *xr, *hh2;
    __half  *xh, *hh, *w1h, *w2h;
    float *pool, *cnt, *y, *bnstat;
    int *deg, *rowptr, *cursor, *col, *bsum;
    cudaGetSymbolAddress((void**)&xl,     g_xl);
    cudaGetSymbolAddress((void**)&xr,     g_xr);
    cudaGetSymbolAddress((void**)&xh,     g_xh);
    cudaGetSymbolAddress((void**)&hh,     g_hh);
    cudaGetSymbolAddress((void**)&w1h,    g_w1h);
    cudaGetSymbolAddress((void**)&w2h,    g_w2h);
    cudaGetSymbolAddress((void**)&pool,   g_pool);
    cudaGetSymbolAddress((void**)&cnt,    g_cnt);
    cudaGetSymbolAddress((void**)&y,      g_y);
    cudaGetSymbolAddress((void**)&bnstat, g_bnstat);
    cudaGetSymbolAddress((void**)&deg,    g_deg);
    cudaGetSymbolAddress((void**)&rowptr, g_rowptr);
    cudaGetSymbolAddress((void**)&cursor, g_cursor);
    cudaGetSymbolAddress((void**)&col,    g_col);
    cudaGetSymbolAddress((void**)&bsum,   g_bsum);
    hh2 = (__half2*)hh;

    dim3 b256(256);
    bool par = (g_aux.s2 != nullptr) && (g_aux.evFork != nullptr) && (g_aux.evB != nullptr);

    detect_kernel<<<1, 1>>>((const int*)ei);

    const int XCONV_GRID = (int)(((size_t)N_NODES * IN_CH / 4 + 255) / 256);

    if (par) {
        cudaEventRecord(g_aux.evFork, 0);
        cudaStreamWaitEvent(g_aux.s2, g_aux.evFork, 0);
        convert_w_kernel<<<(IN_CH * HID + 255) / 256, b256, 0, g_aux.s2>>>(
            W_l1, W_r1, W_l2, W_r2, w1h, w2h);
        convert_x_kernel<<<XCONV_GRID, b256, 0, g_aux.s2>>>(x, (__half2*)xh);
        dual_linear_mma<IN_CH><<<MMA_GRID, b256, 0, g_aux.s2>>>(
            xh, w1h, b_l1, b_r1, xl, xr);
        cudaMemsetAsync(pool, 0, N_GRAPHS * HID * sizeof(float), g_aux.s2);
        cudaMemsetAsync(cnt, 0, N_GRAPHS * sizeof(float), g_aux.s2);
        cudaMemsetAsync(bnstat, 0, 2 * HID * sizeof(float), g_aux.s2);
        cudaEventRecord(g_aux.evB, g_aux.s2);
    }

    // ---- CSR build on stream 0 ----
    cudaMemsetAsync(deg, 0, N_NODES * sizeof(int), 0);
    hist_kernel<<<(E_TOT / 2 + 255) / 256, b256>>>(ei, deg);
    scan1_kernel<<<N_SCAN_BLKS, SCAN_BLK>>>(deg, rowptr, bsum);
    scan2_kernel<<<1, 32>>>(bsum);
    scan3_kernel<<<N_SCAN_BLKS, SCAN_BLK>>>(rowptr, bsum, cursor);
    scatter_kernel<<<(E_TOT / 2 + 255) / 256, b256>>>(ei, cursor, col);

    if (par) {
        cudaStreamWaitEvent(0, g_aux.evB, 0);
    } else {
        convert_w_kernel<<<(IN_CH * HID + 255) / 256, b256>>>(W_l1, W_r1, W_l2, W_r2, w1h, w2h);
        convert_x_kernel<<<XCONV_GRID, b256>>>(x, (__half2*)xh);
        dual_linear_mma<IN_CH><<<MMA_GRID, b256>>>(xh, w1h, b_l1, b_r1, xl, xr);
        cudaMemsetAsync(pool, 0, N_GRAPHS * HID * sizeof(float), 0);
        cudaMemsetAsync(cnt, 0, N_GRAPHS * sizeof(float), 0);
        cudaMemsetAsync(bnstat, 0, 2 * HID * sizeof(float), 0);
    }

    // ---- layer 1 aggregation (writes fp16 h) ----
    gat_agg_kernel<0><<<N_NODES / 32, b256>>>(rowptr, col, xl, xr, att1, bias1,
                                              hh2, 1, batch, pool, cnt);

    // ---- layer 2 (fp16 h in; pool fused into aggregation) ----
    dual_linear_mma<HID><<<MMA_GRID, b256>>>(hh, w2h, b_l2, b_r2, xl, xr);
    gat_agg_kernel<1><<<N_NODES / 32, b256>>>(rowptr, col, xl, xr, att2, bias2,
                                              hh2, 0, batch, pool, cnt);

    // ---- head ----
    fc1_kernel<<<N_GRAPHS, HID>>>(pool, cnt, W_fc1, b_fc1, y, bnstat);
    head_kernel<<<N_GRAPHS, HID>>>(y, bnstat, gamma, beta, W_fc2, b_fc2, out);
}